// round 9
// baseline (speedup 1.0000x reference)
#include <cuda_runtime.h>
#include <cuda_bf16.h>
#include <mma.h>
#include <math.h>

using namespace nvcuda;

#define HIDDEN 128
#define MAX_ING 20000
#define MAX_CMP 10000
#define MAX_EDGE 1000000
#define SPLIT 4   // sub-groups per compound (latency hiding)

// Precomputed per-node projections in bf16 (L2-resident: 5MB + 2.5MB)
__device__ __nv_bfloat16 g_P_ing[MAX_ING * HIDDEN];
__device__ __nv_bfloat16 g_P_cmp[MAX_CMP * HIDDEN];

// CSR-by-compound scratch (re-built every launch; replay-safe)
__device__ int  g_cnt[MAX_CMP];
__device__ int  g_cur[MAX_CMP];
__device__ int  g_off[MAX_CMP + 1];
__device__ int2 g_csr[MAX_EDGE];     // (src_idx, edge_id)

// ---------------------------------------------------------------------------
// CSR build kernels
// ---------------------------------------------------------------------------
__global__ void zero_kernel(int n_cmp)
{
    const int i = blockIdx.x * blockDim.x + threadIdx.x;
    if (i < n_cmp) g_cnt[i] = 0;
}

__global__ void hist_kernel(const int* __restrict__ ei, int E)
{
    const int e = blockIdx.x * blockDim.x + threadIdx.x;
    if (e < E) atomicAdd(&g_cnt[ei[E + e]], 1);
}

// single-block scan over n_cmp counts -> g_off (exclusive+1) and g_cur (exclusive)
__global__ void __launch_bounds__(1024) scan_kernel(int n_cmp)
{
    __shared__ int wsum[32];
    __shared__ int s_carry;
    const int tid = threadIdx.x;
    if (tid == 0) { s_carry = 0; g_off[0] = 0; }
    __syncthreads();

    for (int base = 0; base < n_cmp; base += 1024) {
        const int i = base + tid;
        const int v = (i < n_cmp) ? g_cnt[i] : 0;

        // block inclusive scan
        int x = v;
        #pragma unroll
        for (int o = 1; o < 32; o <<= 1) {
            int n = __shfl_up_sync(0xFFFFFFFFu, x, o);
            if ((tid & 31) >= o) x += n;
        }
        if ((tid & 31) == 31) wsum[tid >> 5] = x;
        __syncthreads();
        if (tid < 32) {
            int w = wsum[tid];
            #pragma unroll
            for (int o = 1; o < 32; o <<= 1) {
                int n = __shfl_up_sync(0xFFFFFFFFu, w, o);
                if (tid >= o) w += n;
            }
            wsum[tid] = w;
        }
        __syncthreads();
        if (tid >= 32) x += wsum[(tid >> 5) - 1];

        const int c = s_carry;
        __syncthreads();
        if (i < n_cmp) {
            g_off[i + 1] = c + x;
            g_cur[i]     = c + x - v;
        }
        if (tid == 1023) s_carry = c + x;   // padded v=0 -> x is chunk total
        __syncthreads();
    }
}

__global__ void scatter_kernel(const int* __restrict__ ei, int E)
{
    const int e = blockIdx.x * blockDim.x + threadIdx.x;
    if (e >= E) return;
    const int s = ei[e];
    const int d = ei[E + e];
    const int pos = atomicAdd(&g_cur[d], 1);
    g_csr[pos] = make_int2(s, e);
}

// ---------------------------------------------------------------------------
// proj v3 (R8-proven): wmma split-bf16, SMEM-staged operands. Unchanged.
// ---------------------------------------------------------------------------
#define A_LD 136
#define W_LD 136
#define SM_A_ELEMS (64 * A_LD)
#define SM_W_ELEMS (128 * W_LD)
#define PROJ_SMEM_BYTES ((2 * SM_A_ELEMS + 2 * SM_W_ELEMS) * 2)

__global__ void __launch_bounds__(256) proj_kernel(
    const float* __restrict__ x_ing,
    const float* __restrict__ x_cmp,
    const float* __restrict__ W1,
    const float* __restrict__ b1,
    int n_ing, int n_cmp, int blocks_ing)
{
    const bool is_cmp = (blockIdx.x >= blocks_ing);
    const float* __restrict__ X = is_cmp ? x_cmp : x_ing;
    const float* __restrict__ W = is_cmp ? (W1 + HIDDEN * HIDDEN) : W1;
    __nv_bfloat16* __restrict__ P = is_cmp ? g_P_cmp : g_P_ing;
    const int nrows = is_cmp ? n_cmp : n_ing;
    const int bid = is_cmp ? (blockIdx.x - blocks_ing) : blockIdx.x;

    const int row0 = bid * 64;
    const int tid = threadIdx.x;
    const int wid = tid >> 5;

    extern __shared__ __align__(16) char sm[];
    __nv_bfloat16* A_hi = reinterpret_cast<__nv_bfloat16*>(sm);
    __nv_bfloat16* A_lo = A_hi + SM_A_ELEMS;
    __nv_bfloat16* W_hi = A_lo + SM_A_ELEMS;
    __nv_bfloat16* W_lo = W_hi + SM_W_ELEMS;

    const float4* __restrict__ Wg4 = reinterpret_cast<const float4*>(W);
    #pragma unroll
    for (int i = 0; i < 16; i++) {
        const int v = tid + i * 256;
        const int r = v >> 5;
        const int c4 = v & 31;
        const float4 w = Wg4[v];
        const float wf[4] = {w.x, w.y, w.z, w.w};
        __nv_bfloat16 h[4], l[4];
        #pragma unroll
        for (int j = 0; j < 4; j++) {
            h[j] = __float2bfloat16_rn(wf[j]);
            l[j] = __float2bfloat16_rn(wf[j] - __bfloat162float(h[j]));
        }
        *reinterpret_cast<uint2*>(&W_hi[r * W_LD + c4 * 4]) = *reinterpret_cast<uint2*>(h);
        *reinterpret_cast<uint2*>(&W_lo[r * W_LD + c4 * 4]) = *reinterpret_cast<uint2*>(l);
    }

    const float4* __restrict__ X4 = reinterpret_cast<const float4*>(X);
    #pragma unroll
    for (int i = 0; i < 8; i++) {
        const int v = tid + i * 256;
        const int r = v >> 5;
        const int c4 = v & 31;
        const int rs = min(row0 + r, nrows - 1);
        const float4 x = X4[(size_t)rs * 32 + c4];
        const float xf[4] = {x.x, x.y, x.z, x.w};
        __nv_bfloat16 h[4], l[4];
        #pragma unroll
        for (int j = 0; j < 4; j++) {
            h[j] = __float2bfloat16_rn(xf[j]);
            l[j] = __float2bfloat16_rn(xf[j] - __bfloat162float(h[j]));
        }
        *reinterpret_cast<uint2*>(&A_hi[r * A_LD + c4 * 4]) = *reinterpret_cast<uint2*>(h);
        *reinterpret_cast<uint2*>(&A_lo[r * A_LD + c4 * 4]) = *reinterpret_cast<uint2*>(l);
    }
    __syncthreads();

    const int warp_r = (wid & 3) * 16;
    const int warp_c = (wid >> 2) * 64;

    wmma::fragment<wmma::accumulator, 16, 16, 16, float> acc[4];
    #pragma unroll
    for (int c = 0; c < 4; c++) wmma::fill_fragment(acc[c], 0.f);

    #pragma unroll
    for (int k = 0; k < 8; k++) {
        wmma::fragment<wmma::matrix_a, 16, 16, 16, __nv_bfloat16, wmma::row_major> a_hi, a_lo;
        wmma::load_matrix_sync(a_hi, &A_hi[warp_r * A_LD + k * 16], A_LD);
        wmma::load_matrix_sync(a_lo, &A_lo[warp_r * A_LD + k * 16], A_LD);
        #pragma unroll
        for (int c = 0; c < 4; c++) {
            const int col = warp_c + c * 16;
            wmma::fragment<wmma::matrix_b, 16, 16, 16, __nv_bfloat16, wmma::row_major> b_hi, b_lo;
            wmma::load_matrix_sync(b_hi, &W_hi[(k * 16) * W_LD + col], W_LD);
            wmma::load_matrix_sync(b_lo, &W_lo[(k * 16) * W_LD + col], W_LD);
            wmma::mma_sync(acc[c], a_hi, b_hi, acc[c]);
            wmma::mma_sync(acc[c], a_hi, b_lo, acc[c]);
            wmma::mma_sync(acc[c], a_lo, b_hi, acc[c]);
        }
    }

    __syncthreads();
    float* Cst = reinterpret_cast<float*>(sm);
    #pragma unroll
    for (int c = 0; c < 4; c++)
        wmma::store_matrix_sync(&Cst[warp_r * 128 + warp_c + c * 16], acc[c],
                                128, wmma::mem_row_major);
    __syncthreads();

    uint2* P2 = reinterpret_cast<uint2*>(P);
    #pragma unroll
    for (int i = 0; i < 8; i++) {
        const int v = tid + i * 256;
        const int r = v >> 5;
        const int c4 = v & 31;
        if (row0 + r < nrows) {
            float4 p = *reinterpret_cast<const float4*>(&Cst[r * 128 + c4 * 4]);
            if (is_cmp) {
                const float4 bv = reinterpret_cast<const float4*>(b1)[c4];
                p.x += bv.x; p.y += bv.y; p.z += bv.z; p.w += bv.w;
            }
            __nv_bfloat162 lo = __float22bfloat162_rn(make_float2(p.x, p.y));
            __nv_bfloat162 hi = __float22bfloat162_rn(make_float2(p.z, p.w));
            uint2 o;
            o.x = *reinterpret_cast<unsigned int*>(&lo);
            o.y = *reinterpret_cast<unsigned int*>(&hi);
            P2[(size_t)(row0 + r) * 32 + c4] = o;
        }
    }
}

// ---------------------------------------------------------------------------
// Edge kernel v7 (CSR): 8-lane group owns (compound, sub) pair; P_cmp row held
// in registers; per edge only P_ing gathered (256B vs 512B). 2-edge unroll.
// ---------------------------------------------------------------------------
__device__ __forceinline__ float pair_dot(
    uint4 al, uint4 ah, uint4 bl, uint4 bh, const float* __restrict__ wv)
{
    const __nv_bfloat162 z2 = __float2bfloat162_rn(0.f);
    const unsigned av[8] = {al.x, al.y, al.z, al.w, ah.x, ah.y, ah.z, ah.w};
    const unsigned bv[8] = {bl.x, bl.y, bl.z, bl.w, bh.x, bh.y, bh.z, bh.w};
    float acc = 0.f;
    #pragma unroll
    for (int j = 0; j < 8; j++) {
        __nv_bfloat162 ha = *reinterpret_cast<const __nv_bfloat162*>(&av[j]);
        __nv_bfloat162 hb = *reinterpret_cast<const __nv_bfloat162*>(&bv[j]);
        __nv_bfloat162 h2 = __hmax2(__hadd2(ha, hb), z2);
        const unsigned hu = *reinterpret_cast<const unsigned*>(&h2);
        acc = fmaf(__uint_as_float(hu << 16),         wv[2 * j],     acc);
        acc = fmaf(__uint_as_float(hu & 0xFFFF0000u), wv[2 * j + 1], acc);
    }
    return acc;
}

__device__ __forceinline__ float grp_reduce(float a)
{
    a += __shfl_xor_sync(0xFFFFFFFFu, a, 1);
    a += __shfl_xor_sync(0xFFFFFFFFu, a, 2);
    a += __shfl_xor_sync(0xFFFFFFFFu, a, 4);
    return a;
}

__global__ void __launch_bounds__(256) edge_csr_kernel(
    const float* __restrict__ W2,
    const float* __restrict__ b2,
    float* __restrict__ out,
    int n_cmp)
{
    const int gid = (blockIdx.x * 256 + threadIdx.x) >> 3;
    const int t = threadIdx.x & 7;
    const int cid = gid >> 2;          // SPLIT = 4
    const int sub = gid & 3;
    if (cid >= n_cmp) return;

    const float4* W24 = reinterpret_cast<const float4*>(W2);
    const float4 wl0 = __ldg(W24 + 2 * t + 0);
    const float4 wl1 = __ldg(W24 + 2 * t + 1);
    const float4 wh0 = __ldg(W24 + 16 + 2 * t + 0);
    const float4 wh1 = __ldg(W24 + 16 + 2 * t + 1);
    const float wv[16] = {wl0.x, wl0.y, wl0.z, wl0.w,
                          wl1.x, wl1.y, wl1.z, wl1.w,
                          wh0.x, wh0.y, wh0.z, wh0.w,
                          wh1.x, wh1.y, wh1.z, wh1.w};
    const float b2v = __ldg(b2);

    // this compound's projection row, kept in registers
    const char* pc = (const char*)g_P_cmp + (size_t)cid * 256 + t * 16;
    const uint4 bl = __ldg(reinterpret_cast<const uint4*>(pc));
    const uint4 bh = __ldg(reinterpret_cast<const uint4*>(pc + 128));

    const int start = g_off[cid];
    const int end   = g_off[cid + 1];

    for (int e = start + sub; e < end; e += 2 * SPLIT) {
        const int e2 = e + SPLIT;
        const int2 p0 = g_csr[e];
        const bool has2 = (e2 < end);
        const int2 p1 = has2 ? g_csr[e2] : p0;

        const char* pa0 = (const char*)g_P_ing + (size_t)p0.x * 256 + t * 16;
        const char* pa1 = (const char*)g_P_ing + (size_t)p1.x * 256 + t * 16;
        const uint4 al0 = __ldcg(reinterpret_cast<const uint4*>(pa0));
        const uint4 ah0 = __ldcg(reinterpret_cast<const uint4*>(pa0 + 128));
        const uint4 al1 = __ldcg(reinterpret_cast<const uint4*>(pa1));
        const uint4 ah1 = __ldcg(reinterpret_cast<const uint4*>(pa1 + 128));

        float a0 = grp_reduce(pair_dot(al0, ah0, bl, bh, wv));
        float a1 = grp_reduce(pair_dot(al1, ah1, bl, bh, wv));

        if (t == 0) {
            out[p0.y] = 1.f / (1.f + __expf(-(a0 + b2v)));
            if (has2) out[p1.y] = 1.f / (1.f + __expf(-(a1 + b2v)));
        }
    }
}

extern "C" void kernel_launch(void* const* d_in, const int* in_sizes, int n_in,
                              void* d_out, int out_size)
{
    const float* x_ing = (const float*)d_in[0];
    const float* x_cmp = (const float*)d_in[1];
    const int*   ei    = (const int*)d_in[2];
    const float* W1    = (const float*)d_in[3];
    const float* b1    = (const float*)d_in[4];
    const float* W2    = (const float*)d_in[5];
    const float* b2    = (const float*)d_in[6];
    float* out = (float*)d_out;

    const int n_ing = in_sizes[0] / HIDDEN;
    const int n_cmp = in_sizes[1] / HIDDEN;
    const int E     = in_sizes[2] / 2;

    // CSR build
    zero_kernel<<<(n_cmp + 255) / 256, 256>>>(n_cmp);
    hist_kernel<<<(E + 255) / 256, 256>>>(ei, E);
    scan_kernel<<<1, 1024>>>(n_cmp);
    scatter_kernel<<<(E + 255) / 256, 256>>>(ei, E);

    // projections (tensor core)
    cudaFuncSetAttribute(proj_kernel,
                         cudaFuncAttributeMaxDynamicSharedMemorySize,
                         PROJ_SMEM_BYTES);
    const int blocks_ing = (n_ing + 63) / 64;
    const int blocks_cmp = (n_cmp + 63) / 64;
    proj_kernel<<<blocks_ing + blocks_cmp, 256, PROJ_SMEM_BYTES>>>(
        x_ing, x_cmp, W1, b1, n_ing, n_cmp, blocks_ing);

    // edges via CSR
    const int ngroups = n_cmp * SPLIT;
    edge_csr_kernel<<<(ngroups * 8 + 255) / 256, 256>>>(W2, b2, out, n_cmp);
}

// round 10
// speedup vs baseline: 1.5592x; 1.5592x over previous
#include <cuda_runtime.h>
#include <cuda_bf16.h>
#include <mma.h>
#include <math.h>

using namespace nvcuda;

#define HIDDEN 128
#define MAX_ING 20000
#define MAX_CMP 10000

// Precomputed per-node projections in bf16 (L2-resident: 5MB + 2.5MB)
__device__ __nv_bfloat16 g_P_ing[MAX_ING * HIDDEN];
__device__ __nv_bfloat16 g_P_cmp[MAX_CMP * HIDDEN];

// ---------------------------------------------------------------------------
// proj v4: persistent blocks. Each block stages its W half (hi/lo split) ONCE,
// then grid-strides over 64-row A chunks. 192 blocks total (128 ing / 64 cmp),
// 2 blocks/SM co-resident (2 x 104KB smem) -> single wave, W traffic 12MB.
// Math identical to R8-proven split-bf16 wmma (xh*Wh + xh*Wl + xl*Wh).
// ---------------------------------------------------------------------------
#define A_LD 136
#define W_LD 136
#define SM_A_ELEMS (64 * A_LD)
#define SM_W_ELEMS (128 * W_LD)
#define PROJ_SMEM_BYTES ((2 * SM_A_ELEMS + 2 * SM_W_ELEMS) * 2)
#define NB_ING 128
#define NB_CMP 64

__global__ void __launch_bounds__(256) proj_kernel(
    const float* __restrict__ x_ing,
    const float* __restrict__ x_cmp,
    const float* __restrict__ W1,
    const float* __restrict__ b1,
    int n_ing, int n_cmp)
{
    const bool is_cmp = (blockIdx.x >= NB_ING);
    const float* __restrict__ X = is_cmp ? x_cmp : x_ing;
    const float* __restrict__ W = is_cmp ? (W1 + HIDDEN * HIDDEN) : W1;
    __nv_bfloat16* __restrict__ P = is_cmp ? g_P_cmp : g_P_ing;
    const int nrows = is_cmp ? n_cmp : n_ing;
    const int bid = is_cmp ? ((int)blockIdx.x - NB_ING) : (int)blockIdx.x;
    const int nb  = is_cmp ? NB_CMP : NB_ING;
    const int nchunks = (nrows + 63) / 64;

    const int tid = threadIdx.x;
    const int wid = tid >> 5;

    extern __shared__ __align__(16) char sm[];
    __nv_bfloat16* A_hi = reinterpret_cast<__nv_bfloat16*>(sm);
    __nv_bfloat16* A_lo = A_hi + SM_A_ELEMS;
    __nv_bfloat16* W_hi = A_lo + SM_A_ELEMS;
    __nv_bfloat16* W_lo = W_hi + SM_W_ELEMS;
    float* Cst = reinterpret_cast<float*>(sm);   // reuses A region between syncs

    // --- stage W half (128x128 fp32) split into bf16 hi/lo: ONCE per block ---
    const float4* __restrict__ Wg4 = reinterpret_cast<const float4*>(W);
    #pragma unroll
    for (int i = 0; i < 16; i++) {
        const int v = tid + i * 256;       // 4096 float4 slots
        const int r = v >> 5;
        const int c4 = v & 31;
        const float4 w = Wg4[v];
        const float wf[4] = {w.x, w.y, w.z, w.w};
        __nv_bfloat16 h[4], l[4];
        #pragma unroll
        for (int j = 0; j < 4; j++) {
            h[j] = __float2bfloat16_rn(wf[j]);
            l[j] = __float2bfloat16_rn(wf[j] - __bfloat162float(h[j]));
        }
        *reinterpret_cast<uint2*>(&W_hi[r * W_LD + c4 * 4]) = *reinterpret_cast<uint2*>(h);
        *reinterpret_cast<uint2*>(&W_lo[r * W_LD + c4 * 4]) = *reinterpret_cast<uint2*>(l);
    }

    const float4* __restrict__ X4 = reinterpret_cast<const float4*>(X);
    const int warp_r = (wid & 3) * 16;
    const int warp_c = (wid >> 2) * 64;

    for (int chunk = bid; chunk < nchunks; chunk += nb) {
        const int row0 = chunk * 64;

        // --- stage A chunk (64x128 fp32) split into bf16 hi/lo ---
        #pragma unroll
        for (int i = 0; i < 8; i++) {
            const int v = tid + i * 256;   // 2048 float4 slots
            const int r = v >> 5;
            const int c4 = v & 31;
            const int rs = min(row0 + r, nrows - 1);
            const float4 x = X4[(size_t)rs * 32 + c4];
            const float xf[4] = {x.x, x.y, x.z, x.w};
            __nv_bfloat16 h[4], l[4];
            #pragma unroll
            for (int j = 0; j < 4; j++) {
                h[j] = __float2bfloat16_rn(xf[j]);
                l[j] = __float2bfloat16_rn(xf[j] - __bfloat162float(h[j]));
            }
            *reinterpret_cast<uint2*>(&A_hi[r * A_LD + c4 * 4]) = *reinterpret_cast<uint2*>(h);
            *reinterpret_cast<uint2*>(&A_lo[r * A_LD + c4 * 4]) = *reinterpret_cast<uint2*>(l);
        }
        __syncthreads();   // A (and W on iter 0) visible

        // --- wmma: 16x64 per warp ---
        wmma::fragment<wmma::accumulator, 16, 16, 16, float> acc[4];
        #pragma unroll
        for (int c = 0; c < 4; c++) wmma::fill_fragment(acc[c], 0.f);

        #pragma unroll
        for (int k = 0; k < 8; k++) {
            wmma::fragment<wmma::matrix_a, 16, 16, 16, __nv_bfloat16, wmma::row_major> a_hi, a_lo;
            wmma::load_matrix_sync(a_hi, &A_hi[warp_r * A_LD + k * 16], A_LD);
            wmma::load_matrix_sync(a_lo, &A_lo[warp_r * A_LD + k * 16], A_LD);
            #pragma unroll
            for (int c = 0; c < 4; c++) {
                const int col = warp_c + c * 16;
                wmma::fragment<wmma::matrix_b, 16, 16, 16, __nv_bfloat16, wmma::row_major> b_hi, b_lo;
                wmma::load_matrix_sync(b_hi, &W_hi[(k * 16) * W_LD + col], W_LD);
                wmma::load_matrix_sync(b_lo, &W_lo[(k * 16) * W_LD + col], W_LD);
                wmma::mma_sync(acc[c], a_hi, b_hi, acc[c]);
                wmma::mma_sync(acc[c], a_hi, b_lo, acc[c]);
                wmma::mma_sync(acc[c], a_lo, b_hi, acc[c]);
            }
        }
        __syncthreads();   // all mma reads of A done before Cst overwrites it

        #pragma unroll
        for (int c = 0; c < 4; c++)
            wmma::store_matrix_sync(&Cst[warp_r * 128 + warp_c + c * 16], acc[c],
                                    128, wmma::mem_row_major);
        __syncthreads();   // Cst complete

        // --- bias (cmp) + bf16 convert + store ---
        uint2* P2 = reinterpret_cast<uint2*>(P);
        #pragma unroll
        for (int i = 0; i < 8; i++) {
            const int v = tid + i * 256;
            const int r = v >> 5;
            const int c4 = v & 31;
            if (row0 + r < nrows) {
                float4 p = *reinterpret_cast<const float4*>(&Cst[r * 128 + c4 * 4]);
                if (is_cmp) {
                    const float4 bv = reinterpret_cast<const float4*>(b1)[c4];
                    p.x += bv.x; p.y += bv.y; p.z += bv.z; p.w += bv.w;
                }
                __nv_bfloat162 lo = __float22bfloat162_rn(make_float2(p.x, p.y));
                __nv_bfloat162 hi = __float22bfloat162_rn(make_float2(p.z, p.w));
                uint2 o;
                o.x = *reinterpret_cast<unsigned int*>(&lo);
                o.y = *reinterpret_cast<unsigned int*>(&hi);
                P2[(size_t)(row0 + r) * 32 + c4] = o;
            }
        }
        __syncthreads();   // Cst reads done before next chunk's A staging
    }
}

// ---------------------------------------------------------------------------
// Edge kernel (R8-proven, byte-identical): 8 lanes/edge, 4 edges/group,
// contiguous 128B-line __ldcg gathers, bit-shift unpack, FFMA dot,
// 3-shuffle reduce, float4 store.
// ---------------------------------------------------------------------------
__device__ __forceinline__ float edge_slice_dot(
    int s, int d, int t, const float* __restrict__ wv)
{
    const char* pa = (const char*)g_P_ing + (size_t)s * 256 + t * 16;
    const char* pb = (const char*)g_P_cmp + (size_t)d * 256 + t * 16;
    const uint4 al = __ldcg(reinterpret_cast<const uint4*>(pa));
    const uint4 ah = __ldcg(reinterpret_cast<const uint4*>(pa + 128));
    const uint4 bl = __ldcg(reinterpret_cast<const uint4*>(pb));
    const uint4 bh = __ldcg(reinterpret_cast<const uint4*>(pb + 128));

    const __nv_bfloat162 z2 = __float2bfloat162_rn(0.f);
    const unsigned av[8] = {al.x, al.y, al.z, al.w, ah.x, ah.y, ah.z, ah.w};
    const unsigned bv[8] = {bl.x, bl.y, bl.z, bl.w, bh.x, bh.y, bh.z, bh.w};

    float acc = 0.f;
    #pragma unroll
    for (int j = 0; j < 8; j++) {
        __nv_bfloat162 ha = *reinterpret_cast<const __nv_bfloat162*>(&av[j]);
        __nv_bfloat162 hb = *reinterpret_cast<const __nv_bfloat162*>(&bv[j]);
        __nv_bfloat162 h2 = __hmax2(__hadd2(ha, hb), z2);
        const unsigned hu = *reinterpret_cast<const unsigned*>(&h2);
        acc = fmaf(__uint_as_float(hu << 16),         wv[2 * j],     acc);
        acc = fmaf(__uint_as_float(hu & 0xFFFF0000u), wv[2 * j + 1], acc);
    }
    return acc;
}

__global__ void __launch_bounds__(256, 6) edge_kernel(
    const int* __restrict__ ei,
    const float* __restrict__ W2,
    const float* __restrict__ b2,
    float* __restrict__ out,
    int E)
{
    const int gid = (blockIdx.x * 256 + threadIdx.x) >> 3;
    const int t = threadIdx.x & 7;
    const int e0 = gid * 4;
    if (e0 >= E) return;

    const float4* W24 = reinterpret_cast<const float4*>(W2);
    const float4 wl0 = __ldg(W24 + 2 * t + 0);
    const float4 wl1 = __ldg(W24 + 2 * t + 1);
    const float4 wh0 = __ldg(W24 + 16 + 2 * t + 0);
    const float4 wh1 = __ldg(W24 + 16 + 2 * t + 1);
    const float wv[16] = {wl0.x, wl0.y, wl0.z, wl0.w,
                          wl1.x, wl1.y, wl1.z, wl1.w,
                          wh0.x, wh0.y, wh0.z, wh0.w,
                          wh1.x, wh1.y, wh1.z, wh1.w};
    const float b2v = __ldg(b2);

    int sv[4], dv[4];
    int ne;
    if (e0 + 4 <= E) {
        ne = 4;
        const int4 s4 = __ldg(reinterpret_cast<const int4*>(ei + e0));
        const int4 d4 = __ldg(reinterpret_cast<const int4*>(ei + E + e0));
        sv[0] = s4.x; sv[1] = s4.y; sv[2] = s4.z; sv[3] = s4.w;
        dv[0] = d4.x; dv[1] = d4.y; dv[2] = d4.z; dv[3] = d4.w;
    } else {
        ne = E - e0;
        for (int i = 0; i < ne; i++) {
            sv[i] = __ldg(ei + e0 + i);
            dv[i] = __ldg(ei + E + e0 + i);
        }
        for (int i = ne; i < 4; i++) { sv[i] = 0; dv[i] = 0; }
    }

    float acc[4];
    #pragma unroll
    for (int i = 0; i < 4; i++)
        acc[i] = edge_slice_dot(sv[i], dv[i], t, wv);

    #pragma unroll
    for (int i = 0; i < 4; i++) {
        acc[i] += __shfl_xor_sync(0xFFFFFFFFu, acc[i], 1);
        acc[i] += __shfl_xor_sync(0xFFFFFFFFu, acc[i], 2);
        acc[i] += __shfl_xor_sync(0xFFFFFFFFu, acc[i], 4);
    }

    if (t == 0) {
        if (ne == 4) {
            float4 o;
            o.x = 1.f / (1.f + __expf(-(acc[0] + b2v)));
            o.y = 1.f / (1.f + __expf(-(acc[1] + b2v)));
            o.z = 1.f / (1.f + __expf(-(acc[2] + b2v)));
            o.w = 1.f / (1.f + __expf(-(acc[3] + b2v)));
            *reinterpret_cast<float4*>(out + e0) = o;
        } else {
            for (int i = 0; i < ne; i++)
                out[e0 + i] = 1.f / (1.f + __expf(-(acc[i] + b2v)));
        }
    }
}

extern "C" void kernel_launch(void* const* d_in, const int* in_sizes, int n_in,
                              void* d_out, int out_size)
{
    const float* x_ing = (const float*)d_in[0];
    const float* x_cmp = (const float*)d_in[1];
    const int*   ei    = (const int*)d_in[2];
    const float* W1    = (const float*)d_in[3];
    const float* b1    = (const float*)d_in[4];
    const float* W2    = (const float*)d_in[5];
    const float* b2    = (const float*)d_in[6];
    float* out = (float*)d_out;

    const int n_ing = in_sizes[0] / HIDDEN;
    const int n_cmp = in_sizes[1] / HIDDEN;
    const int E     = in_sizes[2] / 2;

    cudaFuncSetAttribute(proj_kernel,
                         cudaFuncAttributeMaxDynamicSharedMemorySize,
                         PROJ_SMEM_BYTES);
    proj_kernel<<<NB_ING + NB_CMP, 256, PROJ_SMEM_BYTES>>>(
        x_ing, x_cmp, W1, b1, n_ing, n_cmp);

    const int blocks = (E + 127) / 128;  // 128 edges per 256-thread block
    edge_kernel<<<blocks, 256>>>(ei, W2, b2, out, E);
}

// round 11
// speedup vs baseline: 1.5763x; 1.0110x over previous
#include <cuda_runtime.h>
#include <cuda_bf16.h>
#include <mma.h>
#include <math.h>

using namespace nvcuda;

#define HIDDEN 128
#define MAX_ING 20000
#define MAX_CMP 10000

// Precomputed per-node projections in bf16 (L2-resident: 5MB + 2.5MB)
__device__ __nv_bfloat16 g_P_ing[MAX_ING * HIDDEN];
__device__ __nv_bfloat16 g_P_cmp[MAX_CMP * HIDDEN];

// ---------------------------------------------------------------------------
// proj v5: single-pass TF32 wmma.
// P = X @ W (+bias for cmp). A staged fp32 in smem (clamped rows, pad LD=132),
// B fragments loaded DIRECTLY from global W1 (L1-hot, 64KB per half).
// Block: 256 threads, 64 rows x 128 cols; warp grid 4x2, 16x64 per warp.
// smem: max(64*132, 64*128) floats = 33792B -> high occupancy, 2 syncs total.
// Precision: tf32 input rounding ~2.8e-4 RMS -> element err ~1e-3 on P,
// negligible vs existing 4e-3 bf16 storage err (quadrature).
// ---------------------------------------------------------------------------
#define PAD_LD 132
#define PROJ_SMEM_FLOATS (64 * PAD_LD)

__global__ void __launch_bounds__(256) proj_kernel(
    const float* __restrict__ x_ing,
    const float* __restrict__ x_cmp,
    const float* __restrict__ W1,
    const float* __restrict__ b1,
    int n_ing, int n_cmp, int blocks_ing)
{
    const bool is_cmp = (blockIdx.x >= blocks_ing);
    const float* __restrict__ X = is_cmp ? x_cmp : x_ing;
    const float* __restrict__ W = is_cmp ? (W1 + HIDDEN * HIDDEN) : W1;
    __nv_bfloat16* __restrict__ P = is_cmp ? g_P_cmp : g_P_ing;
    const int nrows = is_cmp ? n_cmp : n_ing;
    const int bid = is_cmp ? ((int)blockIdx.x - blocks_ing) : (int)blockIdx.x;

    const int row0 = bid * 64;
    const int tid = threadIdx.x;
    const int wid = tid >> 5;

    __shared__ __align__(16) float smem_f[PROJ_SMEM_FLOATS];

    // --- stage A tile (64x128 fp32, clamped rows) ---
    const float4* __restrict__ X4 = reinterpret_cast<const float4*>(X);
    #pragma unroll
    for (int i = 0; i < 8; i++) {
        const int v = tid + i * 256;       // 2048 float4 slots
        const int r = v >> 5;              // 0..63
        const int c4 = v & 31;
        const int rs = min(row0 + r, nrows - 1);
        *reinterpret_cast<float4*>(&smem_f[r * PAD_LD + c4 * 4]) =
            X4[(size_t)rs * 32 + c4];
    }
    __syncthreads();

    // --- tf32 wmma mainloop: A from smem, B direct from global ---
    const int warp_r = (wid & 3) * 16;
    const int warp_c = (wid >> 2) * 64;

    wmma::fragment<wmma::accumulator, 16, 16, 8, float> acc[4];
    #pragma unroll
    for (int c = 0; c < 4; c++) wmma::fill_fragment(acc[c], 0.f);

    #pragma unroll
    for (int k = 0; k < 16; k++) {
        wmma::fragment<wmma::matrix_a, 16, 16, 8,
                       wmma::precision::tf32, wmma::row_major> a;
        wmma::load_matrix_sync(a, &smem_f[warp_r * PAD_LD + k * 8], PAD_LD);
        #pragma unroll
        for (int i = 0; i < a.num_elements; i++)
            a.x[i] = wmma::__float_to_tf32(a.x[i]);

        #pragma unroll
        for (int c = 0; c < 4; c++) {
            wmma::fragment<wmma::matrix_b, 16, 16, 8,
                           wmma::precision::tf32, wmma::row_major> b;
            wmma::load_matrix_sync(b, W + (k * 8) * HIDDEN + warp_c + c * 16,
                                   HIDDEN);
            #pragma unroll
            for (int i = 0; i < b.num_elements; i++)
                b.x[i] = wmma::__float_to_tf32(b.x[i]);
            wmma::mma_sync(acc[c], a, b, acc[c]);
        }
    }

    // --- stage fp32 results (reuse smem) ---
    __syncthreads();
    #pragma unroll
    for (int c = 0; c < 4; c++)
        wmma::store_matrix_sync(&smem_f[warp_r * 128 + warp_c + c * 16], acc[c],
                                128, wmma::mem_row_major);
    __syncthreads();

    // --- bias (cmp) + bf16 convert + store ---
    uint2* P2 = reinterpret_cast<uint2*>(P);
    #pragma unroll
    for (int i = 0; i < 8; i++) {
        const int v = tid + i * 256;
        const int r = v >> 5;
        const int c4 = v & 31;
        if (row0 + r < nrows) {
            float4 p = *reinterpret_cast<const float4*>(&smem_f[r * 128 + c4 * 4]);
            if (is_cmp) {
                const float4 bv = reinterpret_cast<const float4*>(b1)[c4];
                p.x += bv.x; p.y += bv.y; p.z += bv.z; p.w += bv.w;
            }
            __nv_bfloat162 lo = __float22bfloat162_rn(make_float2(p.x, p.y));
            __nv_bfloat162 hi = __float22bfloat162_rn(make_float2(p.z, p.w));
            uint2 o;
            o.x = *reinterpret_cast<unsigned int*>(&lo);
            o.y = *reinterpret_cast<unsigned int*>(&hi);
            P2[(size_t)(row0 + r) * 32 + c4] = o;
        }
    }
}

// ---------------------------------------------------------------------------
// Edge kernel (R8-proven, byte-identical): 8 lanes/edge, 4 edges/group,
// contiguous 128B-line __ldcg gathers, bit-shift unpack, FFMA dot,
// 3-shuffle reduce, float4 store. Pinned at chip LTS cap (~11 TB/s) — done.
// ---------------------------------------------------------------------------
__device__ __forceinline__ float edge_slice_dot(
    int s, int d, int t, const float* __restrict__ wv)
{
    const char* pa = (const char*)g_P_ing + (size_t)s * 256 + t * 16;
    const char* pb = (const char*)g_P_cmp + (size_t)d * 256 + t * 16;
    const uint4 al = __ldcg(reinterpret_cast<const uint4*>(pa));
    const uint4 ah = __ldcg(reinterpret_cast<const uint4*>(pa + 128));
    const uint4 bl = __ldcg(reinterpret_cast<const uint4*>(pb));
    const uint4 bh = __ldcg(reinterpret_cast<const uint4*>(pb + 128));

    const __nv_bfloat162 z2 = __float2bfloat162_rn(0.f);
    const unsigned av[8] = {al.x, al.y, al.z, al.w, ah.x, ah.y, ah.z, ah.w};
    const unsigned bv[8] = {bl.x, bl.y, bl.z, bl.w, bh.x, bh.y, bh.z, bh.w};

    float acc = 0.f;
    #pragma unroll
    for (int j = 0; j < 8; j++) {
        __nv_bfloat162 ha = *reinterpret_cast<const __nv_bfloat162*>(&av[j]);
        __nv_bfloat162 hb = *reinterpret_cast<const __nv_bfloat162*>(&bv[j]);
        __nv_bfloat162 h2 = __hmax2(__hadd2(ha, hb), z2);
        const unsigned hu = *reinterpret_cast<const unsigned*>(&h2);
        acc = fmaf(__uint_as_float(hu << 16),         wv[2 * j],     acc);
        acc = fmaf(__uint_as_float(hu & 0xFFFF0000u), wv[2 * j + 1], acc);
    }
    return acc;
}

__global__ void __launch_bounds__(256, 6) edge_kernel(
    const int* __restrict__ ei,
    const float* __restrict__ W2,
    const float* __restrict__ b2,
    float* __restrict__ out,
    int E)
{
    const int gid = (blockIdx.x * 256 + threadIdx.x) >> 3;
    const int t = threadIdx.x & 7;
    const int e0 = gid * 4;
    if (e0 >= E) return;

    const float4* W24 = reinterpret_cast<const float4*>(W2);
    const float4 wl0 = __ldg(W24 + 2 * t + 0);
    const float4 wl1 = __ldg(W24 + 2 * t + 1);
    const float4 wh0 = __ldg(W24 + 16 + 2 * t + 0);
    const float4 wh1 = __ldg(W24 + 16 + 2 * t + 1);
    const float wv[16] = {wl0.x, wl0.y, wl0.z, wl0.w,
                          wl1.x, wl1.y, wl1.z, wl1.w,
                          wh0.x, wh0.y, wh0.z, wh0.w,
                          wh1.x, wh1.y, wh1.z, wh1.w};
    const float b2v = __ldg(b2);

    int sv[4], dv[4];
    int ne;
    if (e0 + 4 <= E) {
        ne = 4;
        const int4 s4 = __ldg(reinterpret_cast<const int4*>(ei + e0));
        const int4 d4 = __ldg(reinterpret_cast<const int4*>(ei + E + e0));
        sv[0] = s4.x; sv[1] = s4.y; sv[2] = s4.z; sv[3] = s4.w;
        dv[0] = d4.x; dv[1] = d4.y; dv[2] = d4.z; dv[3] = d4.w;
    } else {
        ne = E - e0;
        for (int i = 0; i < ne; i++) {
            sv[i] = __ldg(ei + e0 + i);
            dv[i] = __ldg(ei + E + e0 + i);
        }
        for (int i = ne; i < 4; i++) { sv[i] = 0; dv[i] = 0; }
    }

    float acc[4];
    #pragma unroll
    for (int i = 0; i < 4; i++)
        acc[i] = edge_slice_dot(sv[i], dv[i], t, wv);

    #pragma unroll
    for (int i = 0; i < 4; i++) {
        acc[i] += __shfl_xor_sync(0xFFFFFFFFu, acc[i], 1);
        acc[i] += __shfl_xor_sync(0xFFFFFFFFu, acc[i], 2);
        acc[i] += __shfl_xor_sync(0xFFFFFFFFu, acc[i], 4);
    }

    if (t == 0) {
        if (ne == 4) {
            float4 o;
            o.x = 1.f / (1.f + __expf(-(acc[0] + b2v)));
            o.y = 1.f / (1.f + __expf(-(acc[1] + b2v)));
            o.z = 1.f / (1.f + __expf(-(acc[2] + b2v)));
            o.w = 1.f / (1.f + __expf(-(acc[3] + b2v)));
            *reinterpret_cast<float4*>(out + e0) = o;
        } else {
            for (int i = 0; i < ne; i++)
                out[e0 + i] = 1.f / (1.f + __expf(-(acc[i] + b2v)));
        }
    }
}

extern "C" void kernel_launch(void* const* d_in, const int* in_sizes, int n_in,
                              void* d_out, int out_size)
{
    const float* x_ing = (const float*)d_in[0];
    const float* x_cmp = (const float*)d_in[1];
    const int*   ei    = (const int*)d_in[2];
    const float* W1    = (const float*)d_in[3];
    const float* b1    = (const float*)d_in[4];
    const float* W2    = (const float*)d_in[5];
    const float* b2    = (const float*)d_in[6];
    float* out = (float*)d_out;

    const int n_ing = in_sizes[0] / HIDDEN;
    const int n_cmp = in_sizes[1] / HIDDEN;
    const int E     = in_sizes[2] / 2;

    const int blocks_ing = (n_ing + 63) / 64;
    const int blocks_cmp = (n_cmp + 63) / 64;
    proj_kernel<<<blocks_ing + blocks_cmp, 256>>>(x_ing, x_cmp, W1, b1,
                                                  n_ing, n_cmp, blocks_ing);

    const int blocks = (E + 127) / 128;  // 128 edges per 256-thread block
    edge_kernel<<<blocks, 256>>>(ei, W2, b2, out, E);
}

// round 12
// speedup vs baseline: 1.9256x; 1.2216x over previous
#include <cuda_runtime.h>
#include <cuda_bf16.h>
#include <mma.h>
#include <math.h>

using namespace nvcuda;

#define HIDDEN 128
#define MAX_ING 20000
#define MAX_CMP 10000

// Precomputed per-node projections in bf16 (L2-resident: 5MB + 2.5MB)
__device__ __nv_bfloat16 g_P_ing[MAX_ING * HIDDEN];
__device__ __nv_bfloat16 g_P_cmp[MAX_CMP * HIDDEN];

// ---------------------------------------------------------------------------
// proj v6: single-pass plain-bf16 wmma.
// P = X @ W (+bias for cmp). A (64x128) and W half (128x128) converted fp32->
// bf16 into smem once per block; 1 MMA per (k,c) (32/warp vs 96 for split).
// smem: A 64x136 bf16 (17.4KB) + W 128x136 bf16 (34.8KB) = 52224B dynamic
// -> 4 blocks/SM. Precision: bf16 input rounding adds ~9e-4 abs on P (RMS
// 0.58), in quadrature with existing bf16-storage error -> final ~5e-4.
// ---------------------------------------------------------------------------
#define A_LD 136
#define W_LD 136
#define SM_A_ELEMS (64 * A_LD)
#define SM_W_ELEMS (128 * W_LD)
#define PROJ_SMEM_BYTES ((SM_A_ELEMS + SM_W_ELEMS) * 2)   // 52224

__global__ void __launch_bounds__(256) proj_kernel(
    const float* __restrict__ x_ing,
    const float* __restrict__ x_cmp,
    const float* __restrict__ W1,
    const float* __restrict__ b1,
    int n_ing, int n_cmp, int blocks_ing)
{
    const bool is_cmp = (blockIdx.x >= blocks_ing);
    const float* __restrict__ X = is_cmp ? x_cmp : x_ing;
    const float* __restrict__ W = is_cmp ? (W1 + HIDDEN * HIDDEN) : W1;
    __nv_bfloat16* __restrict__ P = is_cmp ? g_P_cmp : g_P_ing;
    const int nrows = is_cmp ? n_cmp : n_ing;
    const int bid = is_cmp ? ((int)blockIdx.x - blocks_ing) : (int)blockIdx.x;

    const int row0 = bid * 64;
    const int tid = threadIdx.x;
    const int wid = tid >> 5;

    extern __shared__ __align__(16) char sm[];
    __nv_bfloat16* A_s = reinterpret_cast<__nv_bfloat16*>(sm);
    __nv_bfloat16* W_s = A_s + SM_A_ELEMS;
    float* Cst = reinterpret_cast<float*>(sm);   // reused after MMA loop

    // --- stage W half (128x128 fp32 -> bf16) ---
    const float4* __restrict__ Wg4 = reinterpret_cast<const float4*>(W);
    #pragma unroll
    for (int i = 0; i < 16; i++) {
        const int v = tid + i * 256;       // 4096 float4 slots
        const int r = v >> 5;
        const int c4 = v & 31;
        const float4 w = Wg4[v];
        __nv_bfloat162 lo = __float22bfloat162_rn(make_float2(w.x, w.y));
        __nv_bfloat162 hi = __float22bfloat162_rn(make_float2(w.z, w.w));
        uint2 o;
        o.x = *reinterpret_cast<unsigned int*>(&lo);
        o.y = *reinterpret_cast<unsigned int*>(&hi);
        *reinterpret_cast<uint2*>(&W_s[r * W_LD + c4 * 4]) = o;
    }

    // --- stage A tile (64x128 fp32 -> bf16, clamped rows) ---
    const float4* __restrict__ X4 = reinterpret_cast<const float4*>(X);
    #pragma unroll
    for (int i = 0; i < 8; i++) {
        const int v = tid + i * 256;       // 2048 float4 slots
        const int r = v >> 5;              // 0..63
        const int c4 = v & 31;
        const int rs = min(row0 + r, nrows - 1);
        const float4 x = X4[(size_t)rs * 32 + c4];
        __nv_bfloat162 lo = __float22bfloat162_rn(make_float2(x.x, x.y));
        __nv_bfloat162 hi = __float22bfloat162_rn(make_float2(x.z, x.w));
        uint2 o;
        o.x = *reinterpret_cast<unsigned int*>(&lo);
        o.y = *reinterpret_cast<unsigned int*>(&hi);
        *reinterpret_cast<uint2*>(&A_s[r * A_LD + c4 * 4]) = o;
    }
    __syncthreads();

    // --- bf16 wmma mainloop: 16x64 per warp, 1 MMA per (k,c) ---
    const int warp_r = (wid & 3) * 16;
    const int warp_c = (wid >> 2) * 64;

    wmma::fragment<wmma::accumulator, 16, 16, 16, float> acc[4];
    #pragma unroll
    for (int c = 0; c < 4; c++) wmma::fill_fragment(acc[c], 0.f);

    #pragma unroll
    for (int k = 0; k < 8; k++) {
        wmma::fragment<wmma::matrix_a, 16, 16, 16, __nv_bfloat16, wmma::row_major> a;
        wmma::load_matrix_sync(a, &A_s[warp_r * A_LD + k * 16], A_LD);
        #pragma unroll
        for (int c = 0; c < 4; c++) {
            wmma::fragment<wmma::matrix_b, 16, 16, 16, __nv_bfloat16, wmma::row_major> b;
            wmma::load_matrix_sync(b, &W_s[(k * 16) * W_LD + warp_c + c * 16], W_LD);
            wmma::mma_sync(acc[c], a, b, acc[c]);
        }
    }
    __syncthreads();   // all MMA smem reads done before Cst overwrite

    #pragma unroll
    for (int c = 0; c < 4; c++)
        wmma::store_matrix_sync(&Cst[warp_r * 128 + warp_c + c * 16], acc[c],
                                128, wmma::mem_row_major);
    __syncthreads();

    // --- bias (cmp) + bf16 convert + store ---
    uint2* P2 = reinterpret_cast<uint2*>(P);
    #pragma unroll
    for (int i = 0; i < 8; i++) {
        const int v = tid + i * 256;
        const int r = v >> 5;
        const int c4 = v & 31;
        if (row0 + r < nrows) {
            float4 p = *reinterpret_cast<const float4*>(&Cst[r * 128 + c4 * 4]);
            if (is_cmp) {
                const float4 bv = reinterpret_cast<const float4*>(b1)[c4];
                p.x += bv.x; p.y += bv.y; p.z += bv.z; p.w += bv.w;
            }
            __nv_bfloat162 lo = __float22bfloat162_rn(make_float2(p.x, p.y));
            __nv_bfloat162 hi = __float22bfloat162_rn(make_float2(p.z, p.w));
            uint2 o;
            o.x = *reinterpret_cast<unsigned int*>(&lo);
            o.y = *reinterpret_cast<unsigned int*>(&hi);
            P2[(size_t)(row0 + r) * 32 + c4] = o;
        }
    }
}

// ---------------------------------------------------------------------------
// Edge kernel (R8-proven, byte-identical): 8 lanes/edge, 4 edges/group,
// contiguous 128B-line __ldcg gathers, bit-shift unpack, FFMA dot,
// 3-shuffle reduce, float4 store. Pinned at chip LTS cap (~11 TB/s) — done.
// ---------------------------------------------------------------------------
__device__ __forceinline__ float edge_slice_dot(
    int s, int d, int t, const float* __restrict__ wv)
{
    const char* pa = (const char*)g_P_ing + (size_t)s * 256 + t * 16;
    const char* pb = (const char*)g_P_cmp + (size_t)d * 256 + t * 16;
    const uint4 al = __ldcg(reinterpret_cast<const uint4*>(pa));
    const uint4 ah = __ldcg(reinterpret_cast<const uint4*>(pa + 128));
    const uint4 bl = __ldcg(reinterpret_cast<const uint4*>(pb));
    const uint4 bh = __ldcg(reinterpret_cast<const uint4*>(pb + 128));

    const __nv_bfloat162 z2 = __float2bfloat162_rn(0.f);
    const unsigned av[8] = {al.x, al.y, al.z, al.w, ah.x, ah.y, ah.z, ah.w};
    const unsigned bv[8] = {bl.x, bl.y, bl.z, bl.w, bh.x, bh.y, bh.z, bh.w};

    float acc = 0.f;
    #pragma unroll
    for (int j = 0; j < 8; j++) {
        __nv_bfloat162 ha = *reinterpret_cast<const __nv_bfloat162*>(&av[j]);
        __nv_bfloat162 hb = *reinterpret_cast<const __nv_bfloat162*>(&bv[j]);
        __nv_bfloat162 h2 = __hmax2(__hadd2(ha, hb), z2);
        const unsigned hu = *reinterpret_cast<const unsigned*>(&h2);
        acc = fmaf(__uint_as_float(hu << 16),         wv[2 * j],     acc);
        acc = fmaf(__uint_as_float(hu & 0xFFFF0000u), wv[2 * j + 1], acc);
    }
    return acc;
}

__global__ void __launch_bounds__(256, 6) edge_kernel(
    const int* __restrict__ ei,
    const float* __restrict__ W2,
    const float* __restrict__ b2,
    float* __restrict__ out,
    int E)
{
    const int gid = (blockIdx.x * 256 + threadIdx.x) >> 3;
    const int t = threadIdx.x & 7;
    const int e0 = gid * 4;
    if (e0 >= E) return;

    const float4* W24 = reinterpret_cast<const float4*>(W2);
    const float4 wl0 = __ldg(W24 + 2 * t + 0);
    const float4 wl1 = __ldg(W24 + 2 * t + 1);
    const float4 wh0 = __ldg(W24 + 16 + 2 * t + 0);
    const float4 wh1 = __ldg(W24 + 16 + 2 * t + 1);
    const float wv[16] = {wl0.x, wl0.y, wl0.z, wl0.w,
                          wl1.x, wl1.y, wl1.z, wl1.w,
                          wh0.x, wh0.y, wh0.z, wh0.w,
                          wh1.x, wh1.y, wh1.z, wh1.w};
    const float b2v = __ldg(b2);

    int sv[4], dv[4];
    int ne;
    if (e0 + 4 <= E) {
        ne = 4;
        const int4 s4 = __ldg(reinterpret_cast<const int4*>(ei + e0));
        const int4 d4 = __ldg(reinterpret_cast<const int4*>(ei + E + e0));
        sv[0] = s4.x; sv[1] = s4.y; sv[2] = s4.z; sv[3] = s4.w;
        dv[0] = d4.x; dv[1] = d4.y; dv[2] = d4.z; dv[3] = d4.w;
    } else {
        ne = E - e0;
        for (int i = 0; i < ne; i++) {
            sv[i] = __ldg(ei + e0 + i);
            dv[i] = __ldg(ei + E + e0 + i);
        }
        for (int i = ne; i < 4; i++) { sv[i] = 0; dv[i] = 0; }
    }

    float acc[4];
    #pragma unroll
    for (int i = 0; i < 4; i++)
        acc[i] = edge_slice_dot(sv[i], dv[i], t, wv);

    #pragma unroll
    for (int i = 0; i < 4; i++) {
        acc[i] += __shfl_xor_sync(0xFFFFFFFFu, acc[i], 1);
        acc[i] += __shfl_xor_sync(0xFFFFFFFFu, acc[i], 2);
        acc[i] += __shfl_xor_sync(0xFFFFFFFFu, acc[i], 4);
    }

    if (t == 0) {
        if (ne == 4) {
            float4 o;
            o.x = 1.f / (1.f + __expf(-(acc[0] + b2v)));
            o.y = 1.f / (1.f + __expf(-(acc[1] + b2v)));
            o.z = 1.f / (1.f + __expf(-(acc[2] + b2v)));
            o.w = 1.f / (1.f + __expf(-(acc[3] + b2v)));
            *reinterpret_cast<float4*>(out + e0) = o;
        } else {
            for (int i = 0; i < ne; i++)
                out[e0 + i] = 1.f / (1.f + __expf(-(acc[i] + b2v)));
        }
    }
}

extern "C" void kernel_launch(void* const* d_in, const int* in_sizes, int n_in,
                              void* d_out, int out_size)
{
    const float* x_ing = (const float*)d_in[0];
    const float* x_cmp = (const float*)d_in[1];
    const int*   ei    = (const int*)d_in[2];
    const float* W1    = (const float*)d_in[3];
    const float* b1    = (const float*)d_in[4];
    const float* W2    = (const float*)d_in[5];
    const float* b2    = (const float*)d_in[6];
    float* out = (float*)d_out;

    const int n_ing = in_sizes[0] / HIDDEN;
    const int n_cmp = in_sizes[1] / HIDDEN;
    const int E     = in_sizes[2] / 2;

    cudaFuncSetAttribute(proj_kernel,
                         cudaFuncAttributeMaxDynamicSharedMemorySize,
                         PROJ_SMEM_BYTES);

    const int blocks_ing = (n_ing + 63) / 64;
    const int blocks_cmp = (n_cmp + 63) / 64;
    proj_kernel<<<blocks_ing + blocks_cmp, 256, PROJ_SMEM_BYTES>>>(
        x_ing, x_cmp, W1, b1, n_ing, n_cmp, blocks_ing);

    const int blocks = (E + 127) / 128;  // 128 edges per 256-thread block
    edge_kernel<<<blocks, 256>>>(ei, W2, b2, out, E);
}